// round 15
// baseline (speedup 1.0000x reference)
#include <cuda_runtime.h>
#include <cuda_fp16.h>
#include <cstdint>

#define BATCH 8
#define NNODE 2048
#define FEAT  128
#define LOG2E 1.4426950408889634f

// ---------------- device scratch (no allocations allowed) -------------------
__device__ __half g_wht[BATCH * FEAT * NNODE];  // WhT fp16, [b][f][n]
__device__ float g_wh1[BATCH * NNODE];          // Wh1 * LOG2E
__device__ float g_wh2[BATCH * NNODE];          // Wh2 * LOG2E
__device__ float g_w2bmax[BATCH * 16];          // per 128-block max of g_wh2

// ---------------- helpers ---------------------------------------------------
__device__ __forceinline__ float leakyf(float x) { return fmaxf(x, 0.2f * x); }

__device__ __forceinline__ uint32_t smem_u32(const void* p) {
    uint32_t a;
    asm("{ .reg .u64 t; cvta.to.shared.u64 t, %1; cvt.u32.u64 %0, t; }"
        : "=r"(a) : "l"(p));
    return a;
}

__device__ __forceinline__ uint32_t pack_h2(float x, float y) {
    __half2 v = __floats2half2_rn(x, y);
    return *reinterpret_cast<uint32_t*>(&v);
}

#define CP_ASYNC16(dst, src)                                                   \
    asm volatile("cp.async.cg.shared.global [%0], [%1], 16;" ::"r"(dst),       \
                 "l"(src) : "memory")
#define CP_COMMIT() asm volatile("cp.async.commit_group;" ::: "memory")
#define CP_WAIT0() asm volatile("cp.async.wait_group 0;" ::: "memory")

#define BAR_SYNC(id)                                                           \
    asm volatile("bar.sync %0, 384;" ::"r"(id) : "memory")
#define BAR_ARRIVE(id)                                                         \
    asm volatile("bar.arrive %0, 384;" ::"r"(id) : "memory")
#define MEMBAR_CTA() asm volatile("membar.cta;" ::: "memory")

#define LDSM4(r, a)                                                            \
    asm volatile(                                                              \
        "ldmatrix.sync.aligned.m8n8.x4.shared.b16 {%0,%1,%2,%3}, [%4];"        \
        : "=r"((r)[0]), "=r"((r)[1]), "=r"((r)[2]), "=r"((r)[3])               \
        : "r"(a))

#define MMA16816(c, A, B0, B1)                                                 \
    asm volatile(                                                              \
        "mma.sync.aligned.m16n8k16.row.col.f32.f16.f16.f32 "                   \
        "{%0,%1,%2,%3}, {%4,%5,%6,%7}, {%8,%9}, {%0,%1,%2,%3};"                \
        : "+f"((c)[0]), "+f"((c)[1]), "+f"((c)[2]), "+f"((c)[3])               \
        : "r"((A)[0]), "r"((A)[1]), "r"((A)[2]), "r"((A)[3]),                  \
          "r"(B0), "r"(B1))

// ============================================================================
// k_linear: WhT[f][n] = sum_k W[f][k] h[n][k] + b[f]  via fp16 mma.sync.
// u1/u2/c1/c2 recomputed per-CTA. Scores via fp32 GEMV (exact path).
// grid (16,8), 256 threads, per block: 128 rows x 128 feats of one batch.
// ============================================================================
static constexpr int LIN_SMEM = 2048 + 128 * 132 * 4 + 2 * 32768;  // 135168

__global__ __launch_bounds__(256, 1) void k_linear(
    const float* __restrict__ h, const float* __restrict__ W,
    const float* __restrict__ Wb, const float* __restrict__ aw) {
    extern __shared__ __align__(16) char dynL[];
    float* u1s = (float*)dynL;              // 128
    float* u2s = u1s + 128;                 // 128
    float* wm = u2s + 128;                  // 8
    float* cc = wm + 8;                     // 2 (c1, c2)
    float* h32 = (float*)(dynL + 2048);     // [128][132]
    char* At = dynL + 2048 + 128 * 132 * 4;
    char* Bt = At + 32768;
    float* up = (float*)Bt;  // temp partials (2KB), consumed before Bt staged

    const int b = blockIdx.y, n0 = blockIdx.x * 128;
    const int t = threadIdx.x, lane = t & 31, wid = t >> 5;

    // ---- phase 1: u partials ----
    {
        const int k = t & 127, fh = (t >> 7) * 64;
        float s1 = 0.f, s2 = 0.f;
#pragma unroll 8
        for (int f = 0; f < 64; f++) {
            float w = W[(size_t)(fh + f) * FEAT + k];
            s1 = fmaf(aw[fh + f], w, s1);
            s2 = fmaf(aw[FEAT + fh + f], w, s2);
        }
        up[(t >> 7) * 128 + k] = s1;
        up[256 + (t >> 7) * 128 + k] = s2;
        if (wid == 0) {
            float c1 = 0.f, c2 = 0.f;
#pragma unroll
            for (int i = 0; i < 4; i++) {
                int f = lane + i * 32;
                float bb = Wb[f];
                c1 = fmaf(bb, aw[f], c1);
                c2 = fmaf(bb, aw[FEAT + f], c2);
            }
#pragma unroll
            for (int o = 16; o >= 1; o >>= 1) {
                c1 += __shfl_xor_sync(~0u, c1, o);
                c2 += __shfl_xor_sync(~0u, c2, o);
            }
            if (lane == 0) { cc[0] = c1; cc[1] = c2; }
        }
    }
    __syncthreads();

    // ---- phase 2: finalize u; stage h32 + At ----
    if (t < 128) {
        u1s[t] = up[t] + up[128 + t];
        u2s[t] = up[256 + t] + up[384 + t];
    }
#pragma unroll
    for (int i = 0; i < 8; i++) {
        int idx = t + i * 256;
        int row = idx >> 4;
        int x = idx & 15;
        const float* hp = &h[((size_t)(b * NNODE + n0 + row)) * FEAT + x * 8];
        float4 h0 = *(const float4*)hp;
        float4 h1 = *(const float4*)(hp + 4);
        *(float4*)&h32[row * 132 + x * 8] = h0;
        *(float4*)&h32[row * 132 + x * 8 + 4] = h1;
        const float* wp = &W[(size_t)row * FEAT + x * 8];
        float4 w0 = *(const float4*)wp;
        float4 w1 = *(const float4*)(wp + 4);
        uint4 pw;
        pw.x = pack_h2(w0.x, w0.y); pw.y = pack_h2(w0.z, w0.w);
        pw.z = pack_h2(w1.x, w1.y); pw.w = pack_h2(w1.z, w1.w);
        *(uint4*)(At + row * 256 + (((uint32_t)(x ^ (row & 7))) << 4)) = pw;
    }
    __syncthreads();

    // ---- phase 3: stage Bt + GEMV ----
#pragma unroll
    for (int i = 0; i < 8; i++) {
        int idx = t + i * 256;
        int row = idx >> 4;
        int x = idx & 15;
        float4 a0 = *(float4*)&h32[row * 132 + x * 8];
        float4 a1 = *(float4*)&h32[row * 132 + x * 8 + 4];
        uint4 p;
        p.x = pack_h2(a0.x, a0.y); p.y = pack_h2(a0.z, a0.w);
        p.z = pack_h2(a1.x, a1.y); p.w = pack_h2(a1.z, a1.w);
        *(uint4*)(Bt + row * 256 + (((uint32_t)(x ^ (row & 7))) << 4)) = p;
    }
    {
        const int row = t >> 1, k0 = (t & 1) * 64;
        float p1 = 0.f, p2 = 0.f;
#pragma unroll 8
        for (int k = 0; k < 64; k++) {
            float hv = h32[row * 132 + k0 + k];
            p1 = fmaf(hv, u1s[k0 + k], p1);
            p2 = fmaf(hv, u2s[k0 + k], p2);
        }
        p1 += __shfl_xor_sync(~0u, p1, 1);
        p2 += __shfl_xor_sync(~0u, p2, 1);
        float w2L = (p2 + cc[1]) * LOG2E;
        if ((t & 1) == 0) {
            g_wh1[b * NNODE + n0 + row] = (p1 + cc[0]) * LOG2E;
            g_wh2[b * NNODE + n0 + row] = w2L;
        }
        float m = w2L;
#pragma unroll
        for (int o = 16; o >= 1; o >>= 1)
            m = fmaxf(m, __shfl_xor_sync(~0u, m, o));
        if (lane == 0) wm[wid] = m;
    }
    __syncthreads();
    if (t == 0) {
        float mm = wm[0];
#pragma unroll
        for (int i = 1; i < 8; i++) mm = fmaxf(mm, wm[i]);
        g_w2bmax[b * 16 + blockIdx.x] = mm;
    }

    // ---- MMA: warp owns 16 f-rows, N=128 ----
    float acc[16][4];
#pragma unroll
    for (int nt = 0; nt < 16; nt++)
#pragma unroll
        for (int q = 0; q < 4; q++) acc[nt][q] = 0.f;

    const uint32_t At_a = smem_u32(At), Bt_a = smem_u32(Bt);
    const uint32_t aoff = (uint32_t)(wid * 16 + (lane & 7) + ((lane >> 3) & 1) * 8) * 256u;
    const uint32_t a_hk = lane >> 4, a_sw = lane & 7;
    const uint32_t boff = (uint32_t)(((lane >> 4) & 1) * 8 + (lane & 7)) * 256u;
    const uint32_t b_hk = (lane >> 3) & 1, b_sw = lane & 7;

#pragma unroll
    for (int kk = 0; kk < 8; kk++) {
        uint32_t ah[4];
        LDSM4(ah, At_a + aoff + ((((uint32_t)(kk * 2) + a_hk) ^ a_sw) << 4));
        uint32_t cb = (((uint32_t)(kk * 2) + b_hk) ^ b_sw) << 4;
#pragma unroll
        for (int ntp = 0; ntp < 8; ntp++) {
            uint32_t bh[4];
            LDSM4(bh, Bt_a + boff + (uint32_t)ntp * 4096u + cb);
            MMA16816(acc[ntp * 2], ah, bh[0], bh[1]);
            MMA16816(acc[ntp * 2 + 1], ah, bh[2], bh[3]);
        }
    }

    // epilogue: +bias, pack fp16, store WhT
    const int rA = wid * 16 + (lane >> 2), rB = rA + 8, q = lane & 3;
    const float biasA = Wb[rA], biasB = Wb[rB];
#pragma unroll
    for (int nt = 0; nt < 16; nt++) {
        uint32_t pa = pack_h2(acc[nt][0] + biasA, acc[nt][1] + biasA);
        uint32_t pb = pack_h2(acc[nt][2] + biasB, acc[nt][3] + biasB);
        *(uint32_t*)&g_wht[((size_t)(b * FEAT + rA)) * NNODE + n0 + nt * 8 + q * 2] = pa;
        *(uint32_t*)&g_wht[((size_t)(b * FEAT + rB)) * NNODE + n0 + nt * 8 + q * 2] = pb;
    }
}

// ============================================================================
// k_attn v4: warp-specialized. CTA = 128 query rows, 384 threads:
//   warps 0-7  = consumers: MMA over double-buffered atile/btile.
//   warps 8-11 = producers: adj LDG + P/exp -> atile, B cp.async -> btile.
// Handshake: named barriers (count 384): full[s]=1+s, empty[s]=3+s.
// SMEM: misc[0,1K) atile0[1K,33K) atile1[33K,65K) btile0[65K,97K)
//       btile1[97K,129K). Chunk = 128 keys, 16 chunks.
// ============================================================================
static constexpr int ATTN_SMEM = 1024 + 4 * 32768;  // 132096

__global__ __launch_bounds__(384, 1) void k_attn(const int* __restrict__ adj,
                                                 float* __restrict__ out) {
    extern __shared__ __align__(16) char dyn[];
    char* atile0 = dyn + 1024;
    char* atile1 = dyn + 1024 + 32768;
    char* btile0 = dyn + 1024 + 65536;
    char* btile1 = dyn + 1024 + 98304;

    const int t = threadIdx.x;
    const int wid = t >> 5, lane = t & 31;
    const int b = blockIdx.x >> 4;
    const int n0 = (blockIdx.x & 15) << 7;

    // batch max
    float* mxs = (float*)dyn;  // consumed before rowsum overlay at end
    if (t < 16) mxs[t] = g_w2bmax[b * 16 + t];
    __syncthreads();
    float mxL = mxs[0];
#pragma unroll
    for (int i = 1; i < 16; i++) mxL = fmaxf(mxL, mxs[i]);
    __syncthreads();

    float* rowsum = (float*)dyn;  // written by producers after main loop

    if (wid >= 8) {
        // ==================== PRODUCERS (warps 8-11) ====================
        const int pw = wid - 8;          // 0..3
        const int rb = pw * 32;          // row base
        const int p = t - 256;           // 0..127 (B-staging identity)
        const int jx = lane * 4;

        float c1r[32], c2r[32];
#pragma unroll
        for (int rr = 0; rr < 32; rr++) {
            float w1L = g_wh1[b * NNODE + n0 + rb + rr];
            float xL = w1L + mxL;
            float MrL = fmaxf(xL, 0.2f * xL);
            c1r[rr] = w1L - MrL;
            c2r[rr] = 0.2f * w1L - MrL;
        }
        __half2 s2acc[32];
#pragma unroll
        for (int rr = 0; rr < 32; rr++) s2acc[rr] = __half2half2(__ushort_as_half(0));

        const int* adj_base = &adj[((size_t)(b * NNODE + n0 + rb)) * NNODE + jx];
        const uint32_t p_chunk = (uint32_t)(lane >> 1);
        const uint32_t p_half = (uint32_t)(lane & 1) * 8;

#pragma unroll 1
        for (int c = 0; c < 16; c++) {
            const int s = c & 1;
            if (c >= 2) BAR_SYNC(3 + s);  // consumers freed buffer s

            // B tile: 16 cp.async per thread
            {
                const uint32_t bb = smem_u32(s ? btile1 : btile0);
#pragma unroll
                for (int it = 0; it < 16; it++) {
                    int f = it * 8 + (p >> 4);
                    const __half* src =
                        &g_wht[((size_t)(b * FEAT + f)) * NNODE + c * 128 + (p & 15) * 8];
                    uint32_t dst = bb + (uint32_t)f * 256u +
                                   ((((uint32_t)(p & 15)) ^ (uint32_t)(f & 7)) << 4);
                    CP_ASYNC16(dst, src);
                }
                CP_COMMIT();
            }

            // P tile: rows rb..rb+31, j = jx..jx+3 of chunk c
            {
                char* at = s ? atile1 : atile0;
                const int j0 = c * 128;
                const float4 w2v = *(const float4*)&g_wh2[b * NNODE + j0 + jx];
                const float w2sx = 0.2f * w2v.x, w2sy = 0.2f * w2v.y;
                const float w2sz = 0.2f * w2v.z, w2sw = 0.2f * w2v.w;
#pragma unroll 4
                for (int rr = 0; rr < 32; rr++) {
                    const int r = rb + rr;
                    const float c1 = c1r[rr], c2 = c2r[rr];
                    const int4 av = *(const int4*)(adj_base + (size_t)rr * NNODE + j0);
                    float y0 = fmaxf(c1 + w2v.x, c2 + w2sx);
                    float y1 = fmaxf(c1 + w2v.y, c2 + w2sy);
                    float y2 = fmaxf(c1 + w2v.z, c2 + w2sz);
                    float y3 = fmaxf(c1 + w2v.w, c2 + w2sw);
                    __half2 e01 = h2exp2(__floats2half2_rn(y0, y1));
                    __half2 e23 = h2exp2(__floats2half2_rn(y2, y3));
                    uint32_t m01 = (((uint32_t)(-av.x)) & 0x0000FFFFu) |
                                   (((uint32_t)(-av.y)) & 0xFFFF0000u);
                    uint32_t m23 = (((uint32_t)(-av.z)) & 0x0000FFFFu) |
                                   (((uint32_t)(-av.w)) & 0xFFFF0000u);
                    uint32_t p01 = *(uint32_t*)&e01 & m01;
                    uint32_t p23 = *(uint32_t*)&e23 & m23;
                    *(uint2*)(at + (uint32_t)r * 256u +
                              ((p_chunk ^ (uint32_t)(r & 7)) << 4) + p_half) =
                        make_uint2(p01, p23);
                    s2acc[rr] = __hadd2(s2acc[rr],
                                        __hadd2(*(__half2*)&p01, *(__half2*)&p23));
                }
            }

            CP_WAIT0();      // B copies landed
            MEMBAR_CTA();    // STS visible to consumers
            BAR_ARRIVE(1 + s);
        }

        // rowsum
#pragma unroll
        for (int rr = 0; rr < 32; rr++) {
            float2 sf = __half22float2(s2acc[rr]);
            float sv = sf.x + sf.y;
#pragma unroll
            for (int o = 16; o >= 1; o >>= 1)
                sv += __shfl_xor_sync(0xffffffffu, sv, o);
            if (lane == 0) rowsum[rb + rr] = sv;
        }
    } else {
        // ==================== CONSUMERS (warps 0-7) ====================
        float acc[16][4];
#pragma unroll
        for (int nt = 0; nt < 16; nt++)
#pragma unroll
            for (int q = 0; q < 4; q++) acc[nt][q] = 0.f;

        const uint32_t aoff =
            (uint32_t)(wid * 16 + (lane & 7) + ((lane >> 3) & 1) * 8) * 256u;
        const uint32_t a_hk = lane >> 4, a_sw = lane & 7;
        const uint32_t boff =
            (uint32_t)(((lane >> 4) & 1) * 8 + (lane & 7)) * 256u;
        const uint32_t b_hk = (lane >> 3) & 1, b_sw = lane & 7;

#pragma unroll 1
        for (int c = 0; c < 16; c++) {
            const int s = c & 1;
            BAR_SYNC(1 + s);  // buffer s full
            const uint32_t at_a = smem_u32(s ? atile1 : atile0);
            const uint32_t bt_a = smem_u32(s ? btile1 : btile0);
#pragma unroll 1
            for (int kk = 0; kk < 8; kk++) {
                uint32_t ah[4];
                LDSM4(ah, at_a + aoff + ((((uint32_t)(kk * 2) + a_hk) ^ a_sw) << 4));
                uint32_t cb = (((uint32_t)(kk * 2) + b_hk) ^ b_sw) << 4;
#pragma unroll
                for (int ntp = 0; ntp < 8; ntp++) {
                    uint32_t bh[4];
                    LDSM4(bh, bt_a + boff + (uint32_t)ntp * 4096u + cb);
                    MMA16816(acc[ntp * 2], ah, bh[0], bh[1]);
                    MMA16816(acc[ntp * 2 + 1], ah, bh[2], bh[3]);
                }
            }
            BAR_ARRIVE(3 + s);  // buffer s free
        }

        __syncthreads();  // producers wrote rowsum

        // epilogue: /rowsum, LayerNorm, leaky (R12 layout)
        const int g = lane >> 2, q = lane & 3;
        const int rA = wid * 16 + g, rB = rA + 8;
        const float invA = 1.f / rowsum[rA];
        const float invB = 1.f / rowsum[rB];

        float vA[32], vB[32];
        float sA = 0.f, qA = 0.f, sB = 0.f, qB = 0.f;
#pragma unroll
        for (int nt = 0; nt < 16; nt++) {
            float a0 = acc[nt][0] * invA, a1 = acc[nt][1] * invA;
            float b0 = acc[nt][2] * invB, b1 = acc[nt][3] * invB;
            vA[nt * 2] = a0; vA[nt * 2 + 1] = a1;
            vB[nt * 2] = b0; vB[nt * 2 + 1] = b1;
            sA += a0 + a1; qA = fmaf(a0, a0, fmaf(a1, a1, qA));
            sB += b0 + b1; qB = fmaf(b0, b0, fmaf(b1, b1, qB));
        }
#pragma unroll
        for (int o = 2; o >= 1; o >>= 1) {
            sA += __shfl_xor_sync(0xffffffffu, sA, o);
            qA += __shfl_xor_sync(0xffffffffu, qA, o);
            sB += __shfl_xor_sync(0xffffffffu, sB, o);
            qB += __shfl_xor_sync(0xffffffffu, qB, o);
        }
        const float muA = sA * (1.f / 128.f);
        const float muB = sB * (1.f / 128.f);
        const float rsA = rsqrtf(qA * (1.f / 128.f) - muA * muA + 1e-5f);
        const float rsB = rsqrtf(qB * (1.f / 128.f) - muB * muB + 1e-5f);

        float* oA = out + ((size_t)(b * NNODE + n0 + rA)) * FEAT;
        float* oB = out + ((size_t)(b * NNODE + n0 + rB)) * FEAT;
#pragma unroll
        for (int nt = 0; nt < 16; nt++) {
            float zA0 = (vA[nt * 2] - muA) * rsA, zA1 = (vA[nt * 2 + 1] - muA) * rsA;
            float zB0 = (vB[nt * 2] - muB) * rsB, zB1 = (vB[nt * 2 + 1] - muB) * rsB;
            *(float2*)&oA[nt * 8 + q * 2] = make_float2(leakyf(zA0), leakyf(zA1));
            *(float2*)&oB[nt * 8 + q * 2] = make_float2(leakyf(zB0), leakyf(zB1));
        }
        return;  // consumers done (producers still need the __syncthreads below)
    }

    __syncthreads();  // producer side of the rowsum handoff barrier
}

// ============================================================================
extern "C" void kernel_launch(void* const* d_in, const int* in_sizes, int n_in,
                              void* d_out, int out_size) {
    const float* h   = (const float*)d_in[0];
    const int*   adj = (const int*)d_in[1];
    const float* Ww  = (const float*)d_in[2];
    const float* Wb  = (const float*)d_in[3];
    const float* aw  = (const float*)d_in[4];
    float* out = (float*)d_out;

    cudaFuncSetAttribute(k_linear, cudaFuncAttributeMaxDynamicSharedMemorySize,
                         LIN_SMEM);
    k_linear<<<dim3(16, 8), 256, LIN_SMEM>>>(h, Ww, Wb, aw);
    cudaFuncSetAttribute(k_attn, cudaFuncAttributeMaxDynamicSharedMemorySize,
                         ATTN_SMEM);
    k_attn<<<128, 384, ATTN_SMEM>>>(adj, out);
}

// round 17
// speedup vs baseline: 1.4257x; 1.4257x over previous
#include <cuda_runtime.h>
#include <cuda_fp16.h>
#include <cstdint>

#define BATCH 8
#define NNODE 2048
#define FEAT  128
#define LOG2E 1.4426950408889634f

// ---------------- device scratch (no allocations allowed) -------------------
__device__ __half g_wht[BATCH * FEAT * NNODE];  // WhT fp16, [b][f][n]
__device__ float g_wh1[BATCH * NNODE];          // Wh1 * LOG2E
__device__ float g_wh2[BATCH * NNODE];          // Wh2 * LOG2E
__device__ float g_w2bmax[BATCH * 16];          // per 128-block max of g_wh2

// ---------------- helpers ---------------------------------------------------
__device__ __forceinline__ float leakyf(float x) { return fmaxf(x, 0.2f * x); }

__device__ __forceinline__ uint32_t smem_u32(const void* p) {
    uint32_t a;
    asm("{ .reg .u64 t; cvta.to.shared.u64 t, %1; cvt.u32.u64 %0, t; }"
        : "=r"(a) : "l"(p));
    return a;
}

__device__ __forceinline__ uint32_t pack_h2(float x, float y) {
    __half2 v = __floats2half2_rn(x, y);
    return *reinterpret_cast<uint32_t*>(&v);
}

#define CP_ASYNC16(dst, src)                                                   \
    asm volatile("cp.async.cg.shared.global [%0], [%1], 16;" ::"r"(dst),       \
                 "l"(src) : "memory")
#define CP_COMMIT() asm volatile("cp.async.commit_group;" ::: "memory")
#define CP_WAIT0() asm volatile("cp.async.wait_group 0;" ::: "memory")

#define LDSM4(r, a)                                                            \
    asm volatile(                                                              \
        "ldmatrix.sync.aligned.m8n8.x4.shared.b16 {%0,%1,%2,%3}, [%4];"        \
        : "=r"((r)[0]), "=r"((r)[1]), "=r"((r)[2]), "=r"((r)[3])               \
        : "r"(a))

#define MMA16816(c, A, B0, B1)                                                 \
    asm volatile(                                                              \
        "mma.sync.aligned.m16n8k16.row.col.f32.f16.f16.f32 "                   \
        "{%0,%1,%2,%3}, {%4,%5,%6,%7}, {%8,%9}, {%0,%1,%2,%3};"                \
        : "+f"((c)[0]), "+f"((c)[1]), "+f"((c)[2]), "+f"((c)[3])               \
        : "r"((A)[0]), "r"((A)[1]), "r"((A)[2]), "r"((A)[3]),                  \
          "r"(B0), "r"(B1))

// ============================================================================
// k_linear: WhT[f][n] = sum_k W[f][k] h[n][k] + b[f]  via fp16 mma.sync.
// u1/u2/c1/c2 recomputed per-CTA. Scores via fp32 GEMV (exact path).
// grid (16,8), 256 threads, per block: 128 rows x 128 feats of one batch.
// ============================================================================
static constexpr int LIN_SMEM = 2048 + 128 * 132 * 4 + 2 * 32768;  // 135168

__global__ __launch_bounds__(256, 1) void k_linear(
    const float* __restrict__ h, const float* __restrict__ W,
    const float* __restrict__ Wb, const float* __restrict__ aw) {
    extern __shared__ __align__(16) char dynL[];
    float* u1s = (float*)dynL;              // 128
    float* u2s = u1s + 128;                 // 128
    float* wm = u2s + 128;                  // 8
    float* cc = wm + 8;                     // 2 (c1, c2)
    float* h32 = (float*)(dynL + 2048);     // [128][132]
    char* At = dynL + 2048 + 128 * 132 * 4;
    char* Bt = At + 32768;
    float* up = (float*)Bt;  // temp partials (2KB), consumed before Bt staged

    const int b = blockIdx.y, n0 = blockIdx.x * 128;
    const int t = threadIdx.x, lane = t & 31, wid = t >> 5;

    // ---- phase 1: u partials ----
    {
        const int k = t & 127, fh = (t >> 7) * 64;
        float s1 = 0.f, s2 = 0.f;
#pragma unroll 8
        for (int f = 0; f < 64; f++) {
            float w = W[(size_t)(fh + f) * FEAT + k];
            s1 = fmaf(aw[fh + f], w, s1);
            s2 = fmaf(aw[FEAT + fh + f], w, s2);
        }
        up[(t >> 7) * 128 + k] = s1;
        up[256 + (t >> 7) * 128 + k] = s2;
        if (wid == 0) {
            float c1 = 0.f, c2 = 0.f;
#pragma unroll
            for (int i = 0; i < 4; i++) {
                int f = lane + i * 32;
                float bb = Wb[f];
                c1 = fmaf(bb, aw[f], c1);
                c2 = fmaf(bb, aw[FEAT + f], c2);
            }
#pragma unroll
            for (int o = 16; o >= 1; o >>= 1) {
                c1 += __shfl_xor_sync(~0u, c1, o);
                c2 += __shfl_xor_sync(~0u, c2, o);
            }
            if (lane == 0) { cc[0] = c1; cc[1] = c2; }
        }
    }
    __syncthreads();

    // ---- phase 2: finalize u; stage h32 + At ----
    if (t < 128) {
        u1s[t] = up[t] + up[128 + t];
        u2s[t] = up[256 + t] + up[384 + t];
    }
#pragma unroll
    for (int i = 0; i < 8; i++) {
        int idx = t + i * 256;
        int row = idx >> 4;
        int x = idx & 15;
        const float* hp = &h[((size_t)(b * NNODE + n0 + row)) * FEAT + x * 8];
        float4 h0 = *(const float4*)hp;
        float4 h1 = *(const float4*)(hp + 4);
        *(float4*)&h32[row * 132 + x * 8] = h0;
        *(float4*)&h32[row * 132 + x * 8 + 4] = h1;
        const float* wp = &W[(size_t)row * FEAT + x * 8];
        float4 w0 = *(const float4*)wp;
        float4 w1 = *(const float4*)(wp + 4);
        uint4 pw;
        pw.x = pack_h2(w0.x, w0.y); pw.y = pack_h2(w0.z, w0.w);
        pw.z = pack_h2(w1.x, w1.y); pw.w = pack_h2(w1.z, w1.w);
        *(uint4*)(At + row * 256 + (((uint32_t)(x ^ (row & 7))) << 4)) = pw;
    }
    __syncthreads();

    // ---- phase 3: stage Bt + GEMV ----
#pragma unroll
    for (int i = 0; i < 8; i++) {
        int idx = t + i * 256;
        int row = idx >> 4;
        int x = idx & 15;
        float4 a0 = *(float4*)&h32[row * 132 + x * 8];
        float4 a1 = *(float4*)&h32[row * 132 + x * 8 + 4];
        uint4 p;
        p.x = pack_h2(a0.x, a0.y); p.y = pack_h2(a0.z, a0.w);
        p.z = pack_h2(a1.x, a1.y); p.w = pack_h2(a1.z, a1.w);
        *(uint4*)(Bt + row * 256 + (((uint32_t)(x ^ (row & 7))) << 4)) = p;
    }
    {
        const int row = t >> 1, k0 = (t & 1) * 64;
        float p1 = 0.f, p2 = 0.f;
#pragma unroll 8
        for (int k = 0; k < 64; k++) {
            float hv = h32[row * 132 + k0 + k];
            p1 = fmaf(hv, u1s[k0 + k], p1);
            p2 = fmaf(hv, u2s[k0 + k], p2);
        }
        p1 += __shfl_xor_sync(~0u, p1, 1);
        p2 += __shfl_xor_sync(~0u, p2, 1);
        float w2L = (p2 + cc[1]) * LOG2E;
        if ((t & 1) == 0) {
            g_wh1[b * NNODE + n0 + row] = (p1 + cc[0]) * LOG2E;
            g_wh2[b * NNODE + n0 + row] = w2L;
        }
        float m = w2L;
#pragma unroll
        for (int o = 16; o >= 1; o >>= 1)
            m = fmaxf(m, __shfl_xor_sync(~0u, m, o));
        if (lane == 0) wm[wid] = m;
    }
    __syncthreads();
    if (t == 0) {
        float mm = wm[0];
#pragma unroll
        for (int i = 1; i < 8; i++) mm = fmaxf(mm, wm[i]);
        g_w2bmax[b * 16 + blockIdx.x] = mm;
    }

    // ---- MMA: warp owns 16 f-rows, N=128 ----
    float acc[16][4];
#pragma unroll
    for (int nt = 0; nt < 16; nt++)
#pragma unroll
        for (int q = 0; q < 4; q++) acc[nt][q] = 0.f;

    const uint32_t At_a = smem_u32(At), Bt_a = smem_u32(Bt);
    const uint32_t aoff = (uint32_t)(wid * 16 + (lane & 7) + ((lane >> 3) & 1) * 8) * 256u;
    const uint32_t a_hk = lane >> 4, a_sw = lane & 7;
    const uint32_t boff = (uint32_t)(((lane >> 4) & 1) * 8 + (lane & 7)) * 256u;
    const uint32_t b_hk = (lane >> 3) & 1, b_sw = lane & 7;

#pragma unroll
    for (int kk = 0; kk < 8; kk++) {
        uint32_t ah[4];
        LDSM4(ah, At_a + aoff + ((((uint32_t)(kk * 2) + a_hk) ^ a_sw) << 4));
        uint32_t cb = (((uint32_t)(kk * 2) + b_hk) ^ b_sw) << 4;
#pragma unroll
        for (int ntp = 0; ntp < 8; ntp++) {
            uint32_t bh[4];
            LDSM4(bh, Bt_a + boff + (uint32_t)ntp * 4096u + cb);
            MMA16816(acc[ntp * 2], ah, bh[0], bh[1]);
            MMA16816(acc[ntp * 2 + 1], ah, bh[2], bh[3]);
        }
    }

    // epilogue: +bias, pack fp16, store WhT
    const int rA = wid * 16 + (lane >> 2), rB = rA + 8, q = lane & 3;
    const float biasA = Wb[rA], biasB = Wb[rB];
#pragma unroll
    for (int nt = 0; nt < 16; nt++) {
        uint32_t pa = pack_h2(acc[nt][0] + biasA, acc[nt][1] + biasA);
        uint32_t pb = pack_h2(acc[nt][2] + biasB, acc[nt][3] + biasB);
        *(uint32_t*)&g_wht[((size_t)(b * FEAT + rA)) * NNODE + n0 + nt * 8 + q * 2] = pa;
        *(uint32_t*)&g_wht[((size_t)(b * FEAT + rB)) * NNODE + n0 + nt * 8 + q * 2] = pb;
    }
}

// ============================================================================
// k_attn v5: P computed DIRECTLY into mma A-fragments (no atile, no A barrier).
// CTA = 128 rows, 8 warps (warp = 16 rows x 128 feats, R12 tiling).
// m16n8k16 A layout per lane: rows g=lane>>2, g+8; cols 2q,2q+1,2q+8,2q+9
// (q = lane&3) within each 16-key step -> adj int2 x4 + w2 float2 x2 LDGs.
// B tile: cp.async double-buffered (chunk cc -> btile[cc&1]), one barrier
// per chunk. Rowsum accumulated from fragments.
// SMEM: misc[0,1K) btile0[1K,33K) btile1[33K,65K).
// ============================================================================
static constexpr int ATTN_SMEM = 1024 + 2 * 32768;  // 66560

__global__ __launch_bounds__(256, 1) void k_attn(const int* __restrict__ adj,
                                                 float* __restrict__ out) {
    extern __shared__ __align__(16) char dyn[];
    char* btile0 = dyn + 1024;
    char* btile1 = dyn + 1024 + 32768;

    const int t = threadIdx.x;
    const int wid = t >> 5, lane = t & 31;
    const int b = blockIdx.x >> 4;
    const int n0 = (blockIdx.x & 15) << 7;

    // batch max (misc region; re-used as rowsum later)
    float* mxs = (float*)dyn;
    if (t < 16) mxs[t] = g_w2bmax[b * 16 + t];
    __syncthreads();
    float mxL = mxs[0];
#pragma unroll
    for (int i = 1; i < 16; i++) mxL = fmaxf(mxL, mxs[i]);
    __syncthreads();

    // fragment row constants: rows row_lo = wid*16 + g, row_hi = +8
    const int g = lane >> 2, cq = (lane & 3) * 2;
    const int row_lo = wid * 16 + g;
    float c1_lo, c2_lo, c1_hi, c2_hi;
    {
        float w1L = g_wh1[b * NNODE + n0 + row_lo];
        float xL = w1L + mxL;
        float MrL = fmaxf(xL, 0.2f * xL);
        c1_lo = w1L - MrL;
        c2_lo = 0.2f * w1L - MrL;
        float w1H = g_wh1[b * NNODE + n0 + row_lo + 8];
        float xH = w1H + mxL;
        float MrH = fmaxf(xH, 0.2f * xH);
        c1_hi = w1H - MrH;
        c2_hi = 0.2f * w1H - MrH;
    }

    float acc[16][4];
#pragma unroll
    for (int nt = 0; nt < 16; nt++)
#pragma unroll
        for (int q = 0; q < 4; q++) acc[nt][q] = 0.f;
    __half2 s_lo = __half2half2(__ushort_as_half(0));
    __half2 s_hi = __half2half2(__ushort_as_half(0));

    const int* adj_lo = &adj[((size_t)(b * NNODE + n0 + row_lo)) * NNODE + cq];
    const int* adj_hi = adj_lo + (size_t)8 * NNODE;
    const float* w2p = &g_wh2[b * NNODE + cq];

    const uint32_t boff = (uint32_t)(((lane >> 4) & 1) * 8 + (lane & 7)) * 256u;
    const uint32_t b_hk = (lane >> 3) & 1, b_sw = lane & 7;

    auto issue_b = [&](int cc, char* bbuf) {
        const uint32_t bb = smem_u32(bbuf);
#pragma unroll
        for (int it = 0; it < 8; it++) {
            int f = it * 16 + (t >> 4);
            const __half* src =
                &g_wht[((size_t)(b * FEAT + f)) * NNODE + cc * 128 + (t & 15) * 8];
            uint32_t dst = bb + (uint32_t)f * 256u +
                           ((((uint32_t)(t & 15)) ^ (uint32_t)(f & 7)) << 4);
            CP_ASYNC16(dst, src);
        }
        CP_COMMIT();
    };

    // masked exp in log2 domain -> fp16x2 (adjacent cols), bit-mask by adj pair
    auto frag = [&](float c1, float c2, float2 w, int ax, int ay) -> uint32_t {
        float y0 = fmaxf(c1 + w.x, c2 + 0.2f * w.x);
        float y1 = fmaxf(c1 + w.y, c2 + 0.2f * w.y);
        __half2 e = h2exp2(__floats2half2_rn(y0, y1));
        uint32_t m = (((uint32_t)(-ax)) & 0x0000FFFFu) |
                     (((uint32_t)(-ay)) & 0xFFFF0000u);
        return *(uint32_t*)&e & m;
    };

    // prologue
    issue_b(0, btile0);
    CP_WAIT0();
    __syncthreads();
    issue_b(1, btile1);  // in flight during chunk 0 compute

#pragma unroll 1
    for (int c = 0; c < 16; c++) {
        const uint32_t bt_a = smem_u32((c & 1) ? btile1 : btile0);
#pragma unroll
        for (int ks = 0; ks < 8; ks++) {
            const int j = c * 128 + ks * 16;
            // per-fragment loads
            const int2 all = *(const int2*)(adj_lo + j);
            const int2 alh = *(const int2*)(adj_lo + j + 8);
            const int2 ahl = *(const int2*)(adj_hi + j);
            const int2 ahh = *(const int2*)(adj_hi + j + 8);
            const float2 wl = *(const float2*)(w2p + j);
            const float2 wh = *(const float2*)(w2p + j + 8);
            // build A fragment
            uint32_t af[4];
            af[0] = frag(c1_lo, c2_lo, wl, all.x, all.y);
            af[1] = frag(c1_hi, c2_hi, wl, ahl.x, ahl.y);
            af[2] = frag(c1_lo, c2_lo, wh, alh.x, alh.y);
            af[3] = frag(c1_hi, c2_hi, wh, ahh.x, ahh.y);
            s_lo = __hadd2(s_lo, __hadd2(*(__half2*)&af[0], *(__half2*)&af[2]));
            s_hi = __hadd2(s_hi, __hadd2(*(__half2*)&af[1], *(__half2*)&af[3]));
            // MMAs
            uint32_t cb = (((uint32_t)(ks * 2) + b_hk) ^ b_sw) << 4;
#pragma unroll
            for (int ntp = 0; ntp < 8; ntp++) {
                uint32_t bh[4];
                LDSM4(bh, bt_a + boff + (uint32_t)ntp * 4096u + cb);
                MMA16816(acc[ntp * 2], af, bh[0], bh[1]);
                MMA16816(acc[ntp * 2 + 1], af, bh[2], bh[3]);
            }
        }
        if (c < 15) {
            CP_WAIT0();       // chunk c+1 B copies landed
            __syncthreads();  // all warps done with btile[c&1]
            if (c < 14) issue_b(c + 2, (c & 1) ? btile1 : btile0);
        }
    }

    // rowsum: reduce over the 4 lanes sharing row g (lane^1, lane^2)
    float* rowsum = (float*)dyn;
    {
        float2 fl = __half22float2(s_lo);
        float2 fh = __half22float2(s_hi);
        float slo = fl.x + fl.y, shi = fh.x + fh.y;
#pragma unroll
        for (int o = 2; o >= 1; o >>= 1) {
            slo += __shfl_xor_sync(0xffffffffu, slo, o);
            shi += __shfl_xor_sync(0xffffffffu, shi, o);
        }
        if ((lane & 3) == 0) {
            rowsum[row_lo] = slo;
            rowsum[row_lo + 8] = shi;
        }
    }
    __syncthreads();

    // epilogue: /rowsum, LayerNorm, leaky (R12 layout: rA=row_lo, rB=row_hi)
    const int q = lane & 3;
    const int rA = row_lo, rB = row_lo + 8;
    const float invA = 1.f / rowsum[rA];
    const float invB = 1.f / rowsum[rB];

    float vA[32], vB[32];
    float sA = 0.f, qA = 0.f, sB = 0.f, qB = 0.f;
#pragma unroll
    for (int nt = 0; nt < 16; nt++) {
        float a0 = acc[nt][0] * invA, a1 = acc[nt][1] * invA;
        float b0 = acc[nt][2] * invB, b1 = acc[nt][3] * invB;
        vA[nt * 2] = a0; vA[nt * 2 + 1] = a1;
        vB[nt * 2] = b0; vB[nt * 2 + 1] = b1;
        sA += a0 + a1; qA = fmaf(a0, a0, fmaf(a1, a1, qA));
        sB += b0 + b1; qB = fmaf(b0, b0, fmaf(b1, b1, qB));
    }
#pragma unroll
    for (int o = 2; o >= 1; o >>= 1) {
        sA += __shfl_xor_sync(0xffffffffu, sA, o);
        qA += __shfl_xor_sync(0xffffffffu, qA, o);
        sB += __shfl_xor_sync(0xffffffffu, sB, o);
        qB += __shfl_xor_sync(0xffffffffu, qB, o);
    }
    const float muA = sA * (1.f / 128.f);
    const float muB = sB * (1.f / 128.f);
    const float rsA = rsqrtf(qA * (1.f / 128.f) - muA * muA + 1e-5f);
    const float rsB = rsqrtf(qB * (1.f / 128.f) - muB * muB + 1e-5f);

    float* oA = out + ((size_t)(b * NNODE + n0 + rA)) * FEAT;
    float* oB = out + ((size_t)(b * NNODE + n0 + rB)) * FEAT;
#pragma unroll
    for (int nt = 0; nt < 16; nt++) {
        float zA0 = (vA[nt * 2] - muA) * rsA, zA1 = (vA[nt * 2 + 1] - muA) * rsA;
        float zB0 = (vB[nt * 2] - muB) * rsB, zB1 = (vB[nt * 2 + 1] - muB) * rsB;
        *(float2*)&oA[nt * 8 + q * 2] = make_float2(leakyf(zA0), leakyf(zA1));
        *(float2*)&oB[nt * 8 + q * 2] = make_float2(leakyf(zB0), leakyf(zB1));
    }
}

// ============================================================================
extern "C" void kernel_launch(void* const* d_in, const int* in_sizes, int n_in,
                              void* d_out, int out_size) {
    const float* h   = (const float*)d_in[0];
    const int*   adj = (const int*)d_in[1];
    const float* Ww  = (const float*)d_in[2];
    const float* Wb  = (const float*)d_in[3];
    const float* aw  = (const float*)d_in[4];
    float* out = (float*)d_out;

    cudaFuncSetAttribute(k_linear, cudaFuncAttributeMaxDynamicSharedMemorySize,
                         LIN_SMEM);
    k_linear<<<dim3(16, 8), 256, LIN_SMEM>>>(h, Ww, Wb, aw);
    cudaFuncSetAttribute(k_attn, cudaFuncAttributeMaxDynamicSharedMemorySize,
                         ATTN_SMEM);
    k_attn<<<128, 256, ATTN_SMEM>>>(adj, out);
}